// round 1
// baseline (speedup 1.0000x reference)
#include <cuda_runtime.h>

#define BB 2
#define DD 64
#define HH 128
#define WW 128
#define NS (BB*DD)
#define PAD 10
#define STR 148   // 128 + 2*10, = 4*37 words, odd word stride -> conflict-light

__device__ float g_slice_sum[NS];
__device__ int   g_slice_cnt[NS];
__device__ int   g_slice_fg[NS];

// One block per (b,d) slice. 512 threads.
// Phase 1 (threads 0..127): vertical capped distance scan per column, both
// polarities, storing g^2 (<=100) as bytes in padded shared rows.
// Phase 2 (all 512): horizontal windowed min (|dx|<=9 is exact below the
// clamp at 10), sqrt, clamp, multiply by y_true, block reduction.
__global__ __launch_bounds__(512, 1)
void edt_slice_kernel(const float* __restrict__ yp, const float* __restrict__ yt)
{
    __shared__ unsigned char gf2[HH][STR];
    __shared__ unsigned char gb2[HH][STR];
    __shared__ float rsum[512];
    __shared__ int   rcnt[512];

    const int slice = blockIdx.x;
    const int t = threadIdx.x;
    const float* yps = yp + (size_t)slice * HH * WW;
    const float* yts = yt + (size_t)slice * HH * WW;

    // Fill pad columns with 100 (pad + dx^2 >= 100 -> never beats the init of 100)
    if (t < HH) {
        #pragma unroll
        for (int k = 0; k < PAD; k++)        { gf2[t][k] = 100; gb2[t][k] = 100; }
        #pragma unroll
        for (int k = PAD + WW; k < STR; k++) { gf2[t][k] = 100; gb2[t][k] = 100; }
    }
    __syncthreads();

    int fgflag = 0;
    if (t < WW) {
        // forward scan (distance to nearest zero above, capped at 10)
        int df = 10, db = 10;
        #pragma unroll 4
        for (int i = 0; i < HH; i++) {
            float v = __ldg(&yps[i * WW + t]);
            int sv = (v > 0.7f) ? 1 : 0;
            fgflag |= sv;
            df = sv ? min(df + 1, 10) : 0;   // edt(s): zeros where s==0
            db = sv ? 0 : min(db + 1, 10);   // edt(1-s): zeros where s==1
            gf2[i][t + PAD] = (unsigned char)df;
            gb2[i][t + PAD] = (unsigned char)db;
        }
        // backward scan + combine; recover sv from forward value (df==0 <=> s==0)
        df = 10; db = 10;
        #pragma unroll 4
        for (int i = HH - 1; i >= 0; i--) {
            int dfo = (int)gf2[i][t + PAD];
            int dbo = (int)gb2[i][t + PAD];
            int sv = (dfo > 0) ? 1 : 0;
            df = sv ? min(df + 1, 10) : 0;
            db = sv ? 0 : min(db + 1, 10);
            int f = min(dfo, df);
            int b = min(dbo, db);
            gf2[i][t + PAD] = (unsigned char)(f * f);
            gb2[i][t + PAD] = (unsigned char)(b * b);
        }
    }
    int anyfg = __syncthreads_or(fgflag);

    // Horizontal pass: thread -> (row, 32-col quarter)
    const int row = t >> 2;
    const int j0  = (t & 3) * 32;
    const unsigned char* rf = &gf2[row][PAD];
    const unsigned char* rb = &gb2[row][PAD];
    const float* yrow = &yts[row * WW];

    float acc = 0.0f;
    int cnt = 0;
    #pragma unroll 4
    for (int jj = 0; jj < 32; jj++) {
        int j = j0 + jj;
        int d2f = 100, d2b = 100;
        #pragma unroll
        for (int dk = -9; dk <= 9; dk++) {
            int c2 = dk * dk;
            d2f = min(d2f, (int)rf[j + dk] + c2);
            d2b = min(d2b, (int)rb[j + dk] + c2);
        }
        float c = sqrtf((float)d2f) + sqrtf((float)d2b);
        c = fminf(c, 10.0f);
        float yv = __ldg(&yrow[j]);
        cnt += (yv != 0.0f) ? 1 : 0;
        acc += c * yv;
    }

    // Block reduction
    rsum[t] = acc;
    rcnt[t] = cnt;
    __syncthreads();
    #pragma unroll
    for (int s = 256; s > 0; s >>= 1) {
        if (t < s) { rsum[t] += rsum[t + s]; rcnt[t] += rcnt[t + s]; }
        __syncthreads();
    }
    if (t == 0) {
        g_slice_sum[slice] = rsum[0];
        g_slice_cnt[slice] = rcnt[0];
        g_slice_fg[slice]  = anyfg;
    }
}

// Single small block: per-batch fg range (argmax semantics: all-false -> [0, D-1]),
// masked sum, global nnz count, final division.
__global__ void finalize_kernel(float* __restrict__ out)
{
    __shared__ float ssum[NS];
    __shared__ int   scnt[NS];
    __shared__ int   sfg[NS];
    int t = threadIdx.x;
    if (t < NS) {
        ssum[t] = g_slice_sum[t];
        scnt[t] = g_slice_cnt[t];
        sfg[t]  = g_slice_fg[t];
    }
    __syncthreads();
    if (t == 0) {
        float total = 0.0f;
        for (int b = 0; b < BB; b++) {
            int first = -1, last = 0;
            for (int d = 0; d < DD; d++) {
                if (sfg[b * DD + d]) { if (first < 0) first = d; last = d; }
            }
            if (first < 0) { first = 0; last = DD - 1; }
            for (int d = first; d <= last; d++) total += ssum[b * DD + d];
        }
        long long c = 0;
        for (int i = 0; i < NS; i++) c += scnt[i];
        out[0] = total / (float)c;
    }
}

extern "C" void kernel_launch(void* const* d_in, const int* in_sizes, int n_in,
                              void* d_out, int out_size)
{
    const float* yp = (const float*)d_in[0];
    const float* yt = (const float*)d_in[1];
    float* out = (float*)d_out;
    edt_slice_kernel<<<NS, 512>>>(yp, yt);
    finalize_kernel<<<1, 128>>>(out);
}

// round 2
// speedup vs baseline: 2.3293x; 2.3293x over previous
#include <cuda_runtime.h>

#define BB 2
#define DD 64
#define HH 128
#define WW 128
#define NS (BB*DD)      // 128 slices
#define NBLK (NS*2)     // 256 blocks, half a slice each
#define BROWS 64        // rows per block
#define PAD 10
#define STRW 148        // u16 stride per shared row (128 + 2*10)

__device__ volatile float g_part_sum[NBLK];
__device__ volatile int   g_part_cnt[NBLK];
__device__ volatile int   g_part_fg[NBLK];
__device__ unsigned int   g_done = 0;

// One block per (slice, half). Vertical capped-distance scans are exact with a
// 10-row halo (cap=10 limits the dependency range), so 256 threads run 2 column
// segments in parallel. df|db packed in one u16; after the backward pass the
// word holds (f^2 | b^2<<8). Horizontal pass: since s is binary, exactly one of
// edt(s), edt(1-s) is nonzero per pixel -> one 19-candidate window min on the
// selected byte plane. Finalize fused via last-block atomic counter.
__global__ __launch_bounds__(256)
void edt_kernel(const float* __restrict__ yp, const float* __restrict__ yt,
                float* __restrict__ out)
{
    __shared__ unsigned short g2[BROWS][STRW];
    __shared__ float wsum[8];
    __shared__ int   wcnt[8];
    __shared__ int   s_islast;
    __shared__ unsigned s_fgw[4];
    __shared__ int s_first[BB], s_last[BB];

    const int blk   = blockIdx.x;
    const int slice = blk >> 1;
    const int R0    = (blk & 1) * BROWS;   // global first row of this block
    const int t     = threadIdx.x;
    const int lane  = t & 31, warp = t >> 5;
    const float* yps = yp + (size_t)slice * HH * WW;
    const float* yts = yt + (size_t)slice * HH * WW;

    // pad columns = (100,100): pad + d^2 never beats an in-window candidate below the clamp
    for (int i = t; i < BROWS * 2 * PAD; i += 256) {
        int r = i / (2 * PAD);
        int p = i - r * 2 * PAD;
        int c = (p < PAD) ? p : (p + WW);
        g2[r][c] = 0x6464;
    }

    // ---------------- vertical pass (2 segments x 128 columns) ----------------
    const int col = t & (WW - 1);
    const int seg = t >> 7;          // 0 or 1
    const int r0  = R0 + seg * 32;   // global first owned row
    const int lr0 = seg * 32;        // local row offset

    int fg = 0;
    int df = 10, db = 10;
    if (r0 > 0) {                    // 10-row warm-up halo above (uniform per warp)
        #pragma unroll
        for (int k = 10; k >= 1; k--) {
            float v = __ldg(&yps[(r0 - k) * WW + col]);
            int sv = v > 0.7f;
            fg |= sv;
            df = sv ? min(df + 1, 10) : 0;
            db = sv ? 0 : min(db + 1, 10);
        }
    }
    #pragma unroll 8
    for (int i = 0; i < 32; i++) {
        float v = __ldg(&yps[(r0 + i) * WW + col]);
        int sv = v > 0.7f;
        fg |= sv;
        df = sv ? min(df + 1, 10) : 0;      // edt(s): zeros where s==0
        db = sv ? 0 : min(db + 1, 10);      // edt(1-s): zeros where s==1
        g2[lr0 + i][col + PAD] = (unsigned short)(df | (db << 8));
    }
    df = 10; db = 10;
    if (r0 + 32 < HH) {              // 10-row warm-up halo below
        #pragma unroll
        for (int k = 10; k >= 1; k--) {
            float v = __ldg(&yps[(r0 + 31 + k) * WW + col]);
            int sv = v > 0.7f;
            df = sv ? min(df + 1, 10) : 0;
            db = sv ? 0 : min(db + 1, 10);
        }
    }
    #pragma unroll 8
    for (int i = 31; i >= 0; i--) {
        unsigned int w = g2[lr0 + i][col + PAD];
        int fo = (int)(w & 255u), bo = (int)(w >> 8);
        int sv = fo > 0;                      // recover s from forward value
        df = sv ? min(df + 1, 10) : 0;
        db = sv ? 0 : min(db + 1, 10);
        int f = min(fo, df), b = min(bo, db);
        g2[lr0 + i][col + PAD] = (unsigned short)((f * f) | ((b * b) << 8));
    }
    int anyfg = __syncthreads_or(fg);

    // ---------------- horizontal pass: warp-per-row, coalesced y_true ----------
    float acc = 0.0f; int cnt = 0;
    #pragma unroll
    for (int rr = 0; rr < 8; rr++) {
        int row = warp * 8 + rr;
        const unsigned char* rowb = (const unsigned char*)&g2[row][0];
        const float* yrow = yts + (size_t)(R0 + row) * WW;
        #pragma unroll
        for (int m = 0; m < 4; m++) {
            int j = lane + m * 32;
            int base = (j + PAD) * 2;
            unsigned int w = *(const unsigned short*)(rowb + base);
            int fo = (int)(w & 255u);
            int sel = (fo > 0) ? 0 : 1;              // pick nonzero polarity plane
            int mn  = (fo > 0) ? fo : (int)(w >> 8); // d=0 candidate
            const unsigned char* p = rowb + sel;
            #pragma unroll
            for (int d = 1; d <= 9; d++) {
                int c2 = d * d;
                mn = min(mn, (int)p[base + 2 * d] + c2);
                mn = min(mn, (int)p[base - 2 * d] + c2);
            }
            float c = fminf(sqrtf((float)mn), 10.0f);
            float y = __ldg(&yrow[j]);
            cnt += (y != 0.0f) ? 1 : 0;
            acc += c * y;
        }
    }

    // ---------------- block reduction ----------------
    #pragma unroll
    for (int o = 16; o > 0; o >>= 1) {
        acc += __shfl_down_sync(0xffffffffu, acc, o);
        cnt += __shfl_down_sync(0xffffffffu, cnt, o);
    }
    if (lane == 0) { wsum[warp] = acc; wcnt[warp] = cnt; }
    __syncthreads();
    if (t == 0) {
        float s = 0.0f; int c = 0;
        #pragma unroll
        for (int i = 0; i < 8; i++) { s += wsum[i]; c += wcnt[i]; }
        g_part_sum[blk] = s;
        g_part_cnt[blk] = c;
        g_part_fg[blk]  = anyfg;
        __threadfence();
        unsigned old = atomicAdd(&g_done, 1u);
        s_islast = (old == NBLK - 1u);
        if (s_islast) g_done = 0;   // self-reset for graph replay
    }
    __syncthreads();
    if (!s_islast) return;

    // ---------------- fused finalize (last block only) ----------------
    __threadfence();
    int f = 0;
    if (t < NS) f = (g_part_fg[2 * t] | g_part_fg[2 * t + 1]);
    unsigned bal = __ballot_sync(0xffffffffu, f != 0);
    if (t < NS && lane == 0) s_fgw[warp] = bal;
    __syncthreads();
    if (t < BB) {
        unsigned long long m = (unsigned long long)s_fgw[2 * t] |
                               ((unsigned long long)s_fgw[2 * t + 1] << 32);
        s_first[t] = m ? (__ffsll((long long)m) - 1) : 0;      // argmax(all-false)=0
        s_last[t]  = m ? (63 - __clzll((long long)m)) : (DD - 1);
    }
    __syncthreads();
    float ms; int mc;
    {
        int sl = t >> 1;
        int b  = sl >> 6;           // slice / DD
        int d  = sl & (DD - 1);
        int in = (d >= s_first[b]) && (d <= s_last[b]);
        ms = in ? g_part_sum[t] : 0.0f;
        mc = g_part_cnt[t];
    }
    #pragma unroll
    for (int o = 16; o > 0; o >>= 1) {
        ms += __shfl_down_sync(0xffffffffu, ms, o);
        mc += __shfl_down_sync(0xffffffffu, mc, o);
    }
    if (lane == 0) { wsum[warp] = ms; wcnt[warp] = mc; }
    __syncthreads();
    if (t == 0) {
        float s = 0.0f; long long c = 0;
        #pragma unroll
        for (int i = 0; i < 8; i++) { s += wsum[i]; c += wcnt[i]; }
        out[0] = s / (float)c;
    }
}

extern "C" void kernel_launch(void* const* d_in, const int* in_sizes, int n_in,
                              void* d_out, int out_size)
{
    const float* yp = (const float*)d_in[0];
    const float* yt = (const float*)d_in[1];
    float* out = (float*)d_out;
    edt_kernel<<<NBLK, 256>>>(yp, yt, out);
}